// round 7
// baseline (speedup 1.0000x reference)
#include <cuda_runtime.h>
#include <cuda_fp16.h>
#include <cstdint>
#include <cstddef>

// ============================================================
// GAT attention head, N=8192, IN_F=128, OUT_F=64
//  h = X@W ; e = LeakyReLU(fs_i + fd_j) masked by adj ; softmax ; P@h ; elu
//
// exp(LR(fs+fd)) = max(E_i*E_j, G_i*G_j), E=exp(f), G=exp(0.2f)
// -> no transcendental in the N^2 loop. Fixed-max softmax (logits bounded)
// -> single pass; fp16 P/h via mma.sync.m16n8k16, fp32 accum + denominators.
//
// j-permutation sigma: k=2q->j=4q, k=2q+1->j=4q+1, k=2q+8->j=4q+2, k=2q+9->j=4q+3.
// A-frag (P): each lane's 4 j's contiguous -> adj via one LDG.128 per row.
// B-frag (H, natural j-layout): words for (b0,b1) are ADJACENT -> one LDS.64.
// H tiles staged gmem->smem by cp.async (no register staging).
// ============================================================

#define NT 8192
#define IN_FEAT 128
#define OUT_FEAT 64
#define SPLITS 8
#define JSPAN (NT / SPLITS)      // 1024
#define JTILE 128
#define NTILES (JSPAN / JTILE)   // 8
#define HROW 288                 // smem row stride: LDS.64 conflict-free

// ---------------- scratch (static device arrays; no allocation) ----------
__device__ __half g_ht[OUT_FEAT * NT];          // h transposed fp16: [f][j]
__device__ float2 g_EGs[NT];                    // (exp(fsrc), exp(0.2 fsrc))
__device__ float2 g_EGd[NT];                    // (exp(fdst), exp(0.2 fdst))
__device__ float  g_num[SPLITS * NT * OUT_FEAT];// partial numerators
__device__ float  g_den[SPLITS * NT];           // partial denominators

// ---------------- helpers ------------------------------------------------
__device__ __forceinline__ uint32_t smem_u32(const void* p) {
    uint32_t a;
    asm("{ .reg .u64 t; cvta.to.shared.u64 t, %1; cvt.u32.u64 %0, t; }"
        : "=r"(a) : "l"(p));
    return a;
}
__device__ __forceinline__ void cp16(uint32_t dst, const void* src) {
    asm volatile("cp.async.cg.shared.global [%0], [%1], 16;" :: "r"(dst), "l"(src));
}
__device__ __forceinline__ void cp8(uint32_t dst, const void* src) {
    asm volatile("cp.async.ca.shared.global [%0], [%1], 8;" :: "r"(dst), "l"(src));
}
#define CP_COMMIT() asm volatile("cp.async.commit_group;" ::: "memory")
#define CP_WAIT0()  asm volatile("cp.async.wait_group 0;" ::: "memory")

__device__ __forceinline__ void mma16816(float* d, uint32_t a0, uint32_t a1,
                                         uint32_t a2, uint32_t a3,
                                         uint32_t b0, uint32_t b1) {
    asm volatile(
        "mma.sync.aligned.m16n8k16.row.col.f32.f16.f16.f32 "
        "{%0,%1,%2,%3}, {%4,%5,%6,%7}, {%8,%9}, {%0,%1,%2,%3};"
        : "+f"(d[0]), "+f"(d[1]), "+f"(d[2]), "+f"(d[3])
        : "r"(a0), "r"(a1), "r"(a2), "r"(a3), "r"(b0), "r"(b1));
}
__device__ __forceinline__ uint32_t packh2(float x, float y) {
    __half2 h = __floats2half2_rn(x, y);
    return *reinterpret_cast<uint32_t*>(&h);
}

// =========================================================================
// Kernel 1: h = X@W ; EG tables ; h^T fp16.
// 256 blocks x 128 threads; warp owns 8 rows (32 rows/block). smem = 48 KB.
// =========================================================================
__global__ void __launch_bounds__(128) prep_kernel(const float* __restrict__ x,
                                                   const float* __restrict__ W,
                                                   const float* __restrict__ a) {
    __shared__ float Ws[IN_FEAT * OUT_FEAT];  // 32 KB
    __shared__ float xs[32 * IN_FEAT];        // 16 KB
    int tid = threadIdx.x;
    int i0 = blockIdx.x * 32;

    {
        const float4* W4 = (const float4*)W;
        float4* Ws4 = (float4*)Ws;
#pragma unroll
        for (int u = 0; u < 16; u++) Ws4[tid + u * 128] = W4[tid + u * 128];
        const float4* x4 = (const float4*)(x + (size_t)i0 * IN_FEAT);
        float4* xs4 = (float4*)xs;
#pragma unroll
        for (int u = 0; u < 8; u++) xs4[tid + u * 128] = x4[tid + u * 128];
    }
    __syncthreads();

    int w = tid >> 5, l = tid & 31;       // warp w: rows w*8 .. w*8+7
    float acc[8][2];
#pragma unroll
    for (int rr = 0; rr < 8; rr++) { acc[rr][0] = 0.f; acc[rr][1] = 0.f; }

#pragma unroll 4
    for (int k4 = 0; k4 < IN_FEAT; k4 += 4) {
        float2 wv[4];
#pragma unroll
        for (int kk = 0; kk < 4; kk++)
            wv[kk] = *(const float2*)&Ws[(k4 + kk) * OUT_FEAT + 2 * l];
#pragma unroll
        for (int rr = 0; rr < 8; rr++) {
            float4 xv = *(const float4*)&xs[(w * 8 + rr) * IN_FEAT + k4];
            acc[rr][0] = fmaf(xv.x, wv[0].x, acc[rr][0]);
            acc[rr][1] = fmaf(xv.x, wv[0].y, acc[rr][1]);
            acc[rr][0] = fmaf(xv.y, wv[1].x, acc[rr][0]);
            acc[rr][1] = fmaf(xv.y, wv[1].y, acc[rr][1]);
            acc[rr][0] = fmaf(xv.z, wv[2].x, acc[rr][0]);
            acc[rr][1] = fmaf(xv.z, wv[2].y, acc[rr][1]);
            acc[rr][0] = fmaf(xv.w, wv[3].x, acc[rr][0]);
            acc[rr][1] = fmaf(xv.w, wv[3].y, acc[rr][1]);
        }
    }

#pragma unroll
    for (int rr = 0; rr < 8; rr++) {
        int i = i0 + w * 8 + rr;
        g_ht[(size_t)(2 * l) * NT + i]     = __float2half(acc[rr][0]);
        g_ht[(size_t)(2 * l + 1) * NT + i] = __float2half(acc[rr][1]);
    }

    float a0 = a[2 * l], a1 = a[2 * l + 1];
    float a2 = a[OUT_FEAT + 2 * l], a3 = a[OUT_FEAT + 2 * l + 1];
#pragma unroll
    for (int rr = 0; rr < 8; rr++) {
        float s = acc[rr][0] * a0 + acc[rr][1] * a1;
        float d = acc[rr][0] * a2 + acc[rr][1] * a3;
#pragma unroll
        for (int off = 16; off; off >>= 1) {
            s += __shfl_xor_sync(0xFFFFFFFFu, s, off);
            d += __shfl_xor_sync(0xFFFFFFFFu, d, off);
        }
        if (l == 0) {
            int i = i0 + w * 8 + rr;
            g_EGs[i] = make_float2(expf(s), expf(0.2f * s));
            g_EGd[i] = make_float2(expf(d), expf(0.2f * d));
        }
    }
}

// =========================================================================
// Kernel 2: fused masked-softmax attention (HMMA, cp.async H pipeline)
// grid (64 row-blocks, SPLITS) = 512 CTAs, 256 threads, 3 CTAs/SM.
// =========================================================================
__global__ void __launch_bounds__(256, 3) attn_kernel(const int* __restrict__ adj) {
    __shared__ __align__(16) char   hbuf[2][OUT_FEAT * HROW];  // 2 x 18432 B
    __shared__ __align__(16) float2 egbuf[2][JTILE];           // 2 x 1 KB

    int tid = threadIdx.x, w = tid >> 5, lane = tid & 31;
    int r = lane >> 2, q = lane & 3;
    int i0 = blockIdx.x * 128;
    int split = blockIdx.y;
    int jbase = split * JSPAN;

    uint32_t hb0 = smem_u32(hbuf[0]), hb1 = smem_u32(hbuf[1]);
    uint32_t eg0 = smem_u32(egbuf[0]), eg1 = smem_u32(egbuf[1]);

    int R0 = i0 + w * 16 + r;
    float2 egs0 = g_EGs[R0];
    float2 egs1 = g_EGs[R0 + 8];

    float acc[8][4];
#pragma unroll
    for (int nt = 0; nt < 8; nt++)
#pragma unroll
        for (int v = 0; v < 4; v++) acc[nt][v] = 0.f;
    float ds0 = 0.f, ds1 = 0.f;

    // stage one tile: 1024 x 16B chunks of H, 4 per thread, + EG (tid<128)
    auto issue_tile = [&](uint32_t hdst, uint32_t edst, int j0) {
#pragma unroll
        for (int u = 0; u < 4; u++) {
            int idx = tid + u * 256, f = idx >> 4, c = idx & 15;
            cp16(hdst + f * HROW + c * 16,
                 &g_ht[(size_t)f * NT + j0 + c * 8]);
        }
        if (tid < JTILE) cp8(edst + tid * 8, &g_EGd[j0 + tid]);
        CP_COMMIT();
    };

    issue_tile(hb0, eg0, jbase);

    const size_t rowA = (size_t)R0 * NT;
    const size_t rowB = (size_t)(R0 + 8) * NT;

    for (int t = 0; t < NTILES; t++) {
        int b = t & 1;
        CP_WAIT0();
        __syncthreads();
        if (t + 1 < NTILES)
            issue_tile(b ? hb0 : hb1, b ? eg0 : eg1, jbase + (t + 1) * JTILE);

        const char*   hb = hbuf[b];
        const float2* eb = egbuf[b];
        int Jt = jbase + t * JTILE;

#pragma unroll
        for (int kk = 0; kk < 8; kk++) {
            int jloc = kk * 16 + 4 * q;                 // lane's 4 contiguous j
            int4 avA = *(const int4*)&adj[rowA + Jt + jloc];
            int4 avB = *(const int4*)&adj[rowB + Jt + jloc];
            float4 egA = *(const float4*)&eb[jloc];     // E,G for j, j+1
            float4 egB = *(const float4*)&eb[jloc + 2]; // E,G for j+2, j+3

            float p00 = avA.x ? fmaxf(egs0.x * egA.x, egs0.y * egA.y) : 0.f;
            float p01 = avA.y ? fmaxf(egs0.x * egA.z, egs0.y * egA.w) : 0.f;
            float p02 = avA.z ? fmaxf(egs0.x * egB.x, egs0.y * egB.y) : 0.f;
            float p03 = avA.w ? fmaxf(egs0.x * egB.z, egs0.y * egB.w) : 0.f;
            float p10 = avB.x ? fmaxf(egs1.x * egA.x, egs1.y * egA.y) : 0.f;
            float p11 = avB.y ? fmaxf(egs1.x * egA.z, egs1.y * egA.w) : 0.f;
            float p12 = avB.z ? fmaxf(egs1.x * egB.x, egs1.y * egB.y) : 0.f;
            float p13 = avB.w ? fmaxf(egs1.x * egB.z, egs1.y * egB.w) : 0.f;

            ds0 += (p00 + p01) + (p02 + p03);
            ds1 += (p10 + p11) + (p12 + p13);

            // sigma: a0=(k=2q,2q+1)->j=4q,4q+1 ; a2=(k=2q+8,2q+9)->j=4q+2,4q+3
            uint32_t A0 = packh2(p00, p01);
            uint32_t A1 = packh2(p10, p11);
            uint32_t A2 = packh2(p02, p03);
            uint32_t A3 = packh2(p12, p13);

            int ko = kk * 32 + q * 8;   // natural layout: b0,b1 adjacent words
#pragma unroll
            for (int nt = 0; nt < 8; nt++) {
                uint2 bb = *(const uint2*)(hb + (nt * 8 + r) * HROW + ko);
                mma16816(acc[nt], A0, A1, A2, A3, bb.x, bb.y);
            }
        }
    }

    // denominator: reduce over the 4 lanes (q) sharing a row
    ds0 += __shfl_xor_sync(0xFFFFFFFFu, ds0, 1);
    ds0 += __shfl_xor_sync(0xFFFFFFFFu, ds0, 2);
    ds1 += __shfl_xor_sync(0xFFFFFFFFu, ds1, 1);
    ds1 += __shfl_xor_sync(0xFFFFFFFFu, ds1, 2);
    if (q == 0) {
        g_den[(size_t)split * NT + R0]     = ds0;
        g_den[(size_t)split * NT + R0 + 8] = ds1;
    }

    // numerators -> gmem partials
    float* gn = &g_num[(size_t)split * NT * OUT_FEAT];
#pragma unroll
    for (int nt = 0; nt < 8; nt++) {
        int col = nt * 8 + q * 2;
        *(float2*)&gn[(size_t)R0 * OUT_FEAT + col]       = make_float2(acc[nt][0], acc[nt][1]);
        *(float2*)&gn[(size_t)(R0 + 8) * OUT_FEAT + col] = make_float2(acc[nt][2], acc[nt][3]);
    }
}

// =========================================================================
// Kernel 3: combine split partials, divide, elu
// =========================================================================
__global__ void __launch_bounds__(256) finalize_kernel(float* __restrict__ out) {
    size_t idx = (size_t)blockIdx.x * 256 + threadIdx.x;
    size_t i = idx >> 6;
    float num = 0.f, den = 0.f;
#pragma unroll
    for (int s = 0; s < SPLITS; s++) {
        num += g_num[(size_t)s * NT * OUT_FEAT + idx];
        den += g_den[(size_t)s * NT + i];
    }
    den = fmaxf(den, 1e-30f);
    float v = num / den;
    out[idx] = v > 0.f ? v : expm1f(v);
}

// =========================================================================
extern "C" void kernel_launch(void* const* d_in, const int* in_sizes, int n_in,
                              void* d_out, int out_size) {
    const float* x   = (const float*)d_in[0];
    const int*   adj = (const int*)d_in[1];
    const float* W   = (const float*)d_in[2];
    const float* a   = (const float*)d_in[3];
    float* out = (float*)d_out;

    prep_kernel<<<NT / 32, 128>>>(x, W, a);
    attn_kernel<<<dim3(64, SPLITS), 256>>>(adj);
    finalize_kernel<<<(NT * OUT_FEAT) / 256, 256>>>(out);
}

// round 8
// speedup vs baseline: 1.2973x; 1.2973x over previous
#include <cuda_runtime.h>
#include <cuda_fp16.h>
#include <cstdint>
#include <cstddef>

// ============================================================
// GAT attention head, N=8192, IN_F=128, OUT_F=64
//  h = X@W ; e = LeakyReLU(fs_i + fd_j) masked by adj ; softmax ; P@h ; elu
//
// exp(LR(fs+fd)) = max(E_i*E_j, G_i*G_j), E=exp(f), G=exp(0.2f)
// -> no transcendental in the N^2 loop. Fixed-max softmax (logits bounded)
// -> single pass; fp16 P/h via mma.sync.m16n8k16, fp32 accum + denominators.
//
// j-permutation sigma: k=2q->j=4q, k=2q+1->j=4q+1, k=2q+8->j=4q+2, k=2q+9->j=4q+3.
// A-frag (P): each lane's 4 j's contiguous -> adj via one LDG.128 per row.
// B-frag (H, natural j-layout): (b0,b1) adjacent words -> one LDS.64.
// H tiles staged gmem->smem by cp.async; adj batched 8x LDG.128 (MLP=8).
// ============================================================

#define NT 8192
#define IN_FEAT 128
#define OUT_FEAT 64
#define SPLITS 8
#define JSPAN (NT / SPLITS)      // 1024
#define JTILE 128
#define NTILES (JSPAN / JTILE)   // 8
#define HROW 288                 // smem row stride: LDS.64 conflict-free

// ---------------- scratch (static device arrays; no allocation) ----------
__device__ __half g_ht[OUT_FEAT * NT];          // h transposed fp16: [f][j]
__device__ float2 g_EGs[NT];                    // (exp(fsrc), exp(0.2 fsrc))
__device__ float2 g_EGd[NT];                    // (exp(fdst), exp(0.2 fdst))
__device__ float  g_num[SPLITS * NT * OUT_FEAT];// partial numerators
__device__ float  g_den[SPLITS * NT];           // partial denominators

// ---------------- helpers ------------------------------------------------
__device__ __forceinline__ uint32_t smem_u32(const void* p) {
    uint32_t a;
    asm("{ .reg .u64 t; cvta.to.shared.u64 t, %1; cvt.u32.u64 %0, t; }"
        : "=r"(a) : "l"(p));
    return a;
}
__device__ __forceinline__ void cp16(uint32_t dst, const void* src) {
    asm volatile("cp.async.cg.shared.global [%0], [%1], 16;" :: "r"(dst), "l"(src));
}
__device__ __forceinline__ void cp8(uint32_t dst, const void* src) {
    asm volatile("cp.async.ca.shared.global [%0], [%1], 8;" :: "r"(dst), "l"(src));
}
#define CP_COMMIT() asm volatile("cp.async.commit_group;" ::: "memory")
#define CP_WAIT0()  asm volatile("cp.async.wait_group 0;" ::: "memory")

__device__ __forceinline__ void mma16816(float* d, uint32_t a0, uint32_t a1,
                                         uint32_t a2, uint32_t a3,
                                         uint32_t b0, uint32_t b1) {
    asm volatile(
        "mma.sync.aligned.m16n8k16.row.col.f32.f16.f16.f32 "
        "{%0,%1,%2,%3}, {%4,%5,%6,%7}, {%8,%9}, {%0,%1,%2,%3};"
        : "+f"(d[0]), "+f"(d[1]), "+f"(d[2]), "+f"(d[3])
        : "r"(a0), "r"(a1), "r"(a2), "r"(a3), "r"(b0), "r"(b1));
}
__device__ __forceinline__ uint32_t packh2(float x, float y) {
    __half2 h = __floats2half2_rn(x, y);
    return *reinterpret_cast<uint32_t*>(&h);
}

// =========================================================================
// Kernel 1: h = X@W ; EG tables ; h^T fp16.
// 512 blocks x 128 threads; warp owns 4 rows (16 rows/block); smem = 40 KB.
// =========================================================================
__global__ void __launch_bounds__(128) prep_kernel(const float* __restrict__ x,
                                                   const float* __restrict__ W,
                                                   const float* __restrict__ a) {
    __shared__ float Ws[IN_FEAT * OUT_FEAT];  // 32 KB
    __shared__ float xs[16 * IN_FEAT];        // 8 KB
    int tid = threadIdx.x;
    int i0 = blockIdx.x * 16;

    {
        const float4* W4 = (const float4*)W;
        float4* Ws4 = (float4*)Ws;
#pragma unroll
        for (int u = 0; u < 16; u++) Ws4[tid + u * 128] = W4[tid + u * 128];
        const float4* x4 = (const float4*)(x + (size_t)i0 * IN_FEAT);
        float4* xs4 = (float4*)xs;
#pragma unroll
        for (int u = 0; u < 4; u++) xs4[tid + u * 128] = x4[tid + u * 128];
    }
    __syncthreads();

    int w = tid >> 5, l = tid & 31;       // warp w: rows w*4 .. w*4+3
    float acc[4][2];
#pragma unroll
    for (int rr = 0; rr < 4; rr++) { acc[rr][0] = 0.f; acc[rr][1] = 0.f; }

#pragma unroll 4
    for (int k4 = 0; k4 < IN_FEAT; k4 += 4) {
        float2 wv[4];
#pragma unroll
        for (int kk = 0; kk < 4; kk++)
            wv[kk] = *(const float2*)&Ws[(k4 + kk) * OUT_FEAT + 2 * l];
#pragma unroll
        for (int rr = 0; rr < 4; rr++) {
            float4 xv = *(const float4*)&xs[(w * 4 + rr) * IN_FEAT + k4];
            acc[rr][0] = fmaf(xv.x, wv[0].x, acc[rr][0]);
            acc[rr][1] = fmaf(xv.x, wv[0].y, acc[rr][1]);
            acc[rr][0] = fmaf(xv.y, wv[1].x, acc[rr][0]);
            acc[rr][1] = fmaf(xv.y, wv[1].y, acc[rr][1]);
            acc[rr][0] = fmaf(xv.z, wv[2].x, acc[rr][0]);
            acc[rr][1] = fmaf(xv.z, wv[2].y, acc[rr][1]);
            acc[rr][0] = fmaf(xv.w, wv[3].x, acc[rr][0]);
            acc[rr][1] = fmaf(xv.w, wv[3].y, acc[rr][1]);
        }
    }

#pragma unroll
    for (int rr = 0; rr < 4; rr++) {
        int i = i0 + w * 4 + rr;
        g_ht[(size_t)(2 * l) * NT + i]     = __float2half(acc[rr][0]);
        g_ht[(size_t)(2 * l + 1) * NT + i] = __float2half(acc[rr][1]);
    }

    float a0 = a[2 * l], a1 = a[2 * l + 1];
    float a2 = a[OUT_FEAT + 2 * l], a3 = a[OUT_FEAT + 2 * l + 1];
#pragma unroll
    for (int rr = 0; rr < 4; rr++) {
        float s = acc[rr][0] * a0 + acc[rr][1] * a1;
        float d = acc[rr][0] * a2 + acc[rr][1] * a3;
#pragma unroll
        for (int off = 16; off; off >>= 1) {
            s += __shfl_xor_sync(0xFFFFFFFFu, s, off);
            d += __shfl_xor_sync(0xFFFFFFFFu, d, off);
        }
        if (l == 0) {
            int i = i0 + w * 4 + rr;
            g_EGs[i] = make_float2(expf(s), expf(0.2f * s));
            g_EGd[i] = make_float2(expf(d), expf(0.2f * d));
        }
    }
}

// =========================================================================
// Kernel 2: fused masked-softmax attention (HMMA, cp.async H pipeline,
// batched adj loads). grid (64, SPLITS) = 512 CTAs, 256 thr, 2 CTAs/SM.
// =========================================================================
__global__ void __launch_bounds__(256, 2) attn_kernel(const int* __restrict__ adj) {
    __shared__ __align__(16) char   hbuf[2][OUT_FEAT * HROW];  // 2 x 18432 B
    __shared__ __align__(16) float2 egbuf[2][JTILE];           // 2 x 1 KB

    int tid = threadIdx.x, w = tid >> 5, lane = tid & 31;
    int r = lane >> 2, q = lane & 3;
    int i0 = blockIdx.x * 128;
    int split = blockIdx.y;
    int jbase = split * JSPAN;

    uint32_t hb0 = smem_u32(hbuf[0]), hb1 = smem_u32(hbuf[1]);
    uint32_t eg0 = smem_u32(egbuf[0]), eg1 = smem_u32(egbuf[1]);

    int R0 = i0 + w * 16 + r;
    float2 egs0 = g_EGs[R0];
    float2 egs1 = g_EGs[R0 + 8];

    float acc[8][4];
#pragma unroll
    for (int nt = 0; nt < 8; nt++)
#pragma unroll
        for (int v = 0; v < 4; v++) acc[nt][v] = 0.f;
    float ds0 = 0.f, ds1 = 0.f;

    // stage one tile: H (64x128 fp16) + EG (128 float2) via cp.async
    auto issue_tile = [&](uint32_t hdst, uint32_t edst, int j0) {
#pragma unroll
        for (int u = 0; u < 4; u++) {
            int idx = tid + u * 256, f = idx >> 4, c = idx & 15;
            cp16(hdst + f * HROW + c * 16,
                 &g_ht[(size_t)f * NT + j0 + c * 8]);
        }
        if (tid < JTILE) cp8(edst + tid * 8, &g_EGd[j0 + tid]);
        CP_COMMIT();
    };

    issue_tile(hb0, eg0, jbase);

    const size_t rowA = (size_t)R0 * NT;
    const size_t rowB = (size_t)(R0 + 8) * NT;

    for (int t = 0; t < NTILES; t++) {
        int b = t & 1;
        CP_WAIT0();
        __syncthreads();
        if (t + 1 < NTILES)
            issue_tile(b ? hb0 : hb1, b ? eg0 : eg1, jbase + (t + 1) * JTILE);

        const char*   hb = hbuf[b];
        const float2* eb = egbuf[b];
        int Jt = jbase + t * JTILE;

#pragma unroll
        for (int h2 = 0; h2 < 2; h2++) {
            // batch-load adj for 4 kk steps: 8x LDG.128 in flight (MLP=8)
            int4 aA[4], aB[4];
#pragma unroll
            for (int k2 = 0; k2 < 4; k2++) {
                int jloc = (h2 * 4 + k2) * 16 + 4 * q;
                aA[k2] = __ldcs((const int4*)&adj[rowA + Jt + jloc]);
                aB[k2] = __ldcs((const int4*)&adj[rowB + Jt + jloc]);
            }
#pragma unroll
            for (int k2 = 0; k2 < 4; k2++) {
                int kk = h2 * 4 + k2;
                int jloc = kk * 16 + 4 * q;
                float4 egA = *(const float4*)&eb[jloc];     // E,G: j, j+1
                float4 egB = *(const float4*)&eb[jloc + 2]; // E,G: j+2, j+3

                float p00 = aA[k2].x ? fmaxf(egs0.x * egA.x, egs0.y * egA.y) : 0.f;
                float p01 = aA[k2].y ? fmaxf(egs0.x * egA.z, egs0.y * egA.w) : 0.f;
                float p02 = aA[k2].z ? fmaxf(egs0.x * egB.x, egs0.y * egB.y) : 0.f;
                float p03 = aA[k2].w ? fmaxf(egs0.x * egB.z, egs0.y * egB.w) : 0.f;
                float p10 = aB[k2].x ? fmaxf(egs1.x * egA.x, egs1.y * egA.y) : 0.f;
                float p11 = aB[k2].y ? fmaxf(egs1.x * egA.z, egs1.y * egA.w) : 0.f;
                float p12 = aB[k2].z ? fmaxf(egs1.x * egB.x, egs1.y * egB.y) : 0.f;
                float p13 = aB[k2].w ? fmaxf(egs1.x * egB.z, egs1.y * egB.w) : 0.f;

                ds0 += (p00 + p01) + (p02 + p03);
                ds1 += (p10 + p11) + (p12 + p13);

                uint32_t A0 = packh2(p00, p01);
                uint32_t A1 = packh2(p10, p11);
                uint32_t A2 = packh2(p02, p03);
                uint32_t A3 = packh2(p12, p13);

                int ko = kk * 32 + q * 8;
#pragma unroll
                for (int nt = 0; nt < 8; nt++) {
                    uint2 bb = *(const uint2*)(hb + (nt * 8 + r) * HROW + ko);
                    mma16816(acc[nt], A0, A1, A2, A3, bb.x, bb.y);
                }
            }
        }
    }

    // denominator: reduce over the 4 lanes (q) sharing a row
    ds0 += __shfl_xor_sync(0xFFFFFFFFu, ds0, 1);
    ds0 += __shfl_xor_sync(0xFFFFFFFFu, ds0, 2);
    ds1 += __shfl_xor_sync(0xFFFFFFFFu, ds1, 1);
    ds1 += __shfl_xor_sync(0xFFFFFFFFu, ds1, 2);
    if (q == 0) {
        g_den[(size_t)split * NT + R0]     = ds0;
        g_den[(size_t)split * NT + R0 + 8] = ds1;
    }

    // numerators -> gmem partials
    float* gn = &g_num[(size_t)split * NT * OUT_FEAT];
#pragma unroll
    for (int nt = 0; nt < 8; nt++) {
        int col = nt * 8 + q * 2;
        *(float2*)&gn[(size_t)R0 * OUT_FEAT + col]       = make_float2(acc[nt][0], acc[nt][1]);
        *(float2*)&gn[(size_t)(R0 + 8) * OUT_FEAT + col] = make_float2(acc[nt][2], acc[nt][3]);
    }
}

// =========================================================================
// Kernel 3: combine split partials, divide, elu
// =========================================================================
__global__ void __launch_bounds__(256) finalize_kernel(float* __restrict__ out) {
    size_t idx = (size_t)blockIdx.x * 256 + threadIdx.x;
    size_t i = idx >> 6;
    float num = 0.f, den = 0.f;
#pragma unroll
    for (int s = 0; s < SPLITS; s++) {
        num += g_num[(size_t)s * NT * OUT_FEAT + idx];
        den += g_den[(size_t)s * NT + i];
    }
    den = fmaxf(den, 1e-30f);
    float v = num / den;
    out[idx] = v > 0.f ? v : expm1f(v);
}

// =========================================================================
extern "C" void kernel_launch(void* const* d_in, const int* in_sizes, int n_in,
                              void* d_out, int out_size) {
    const float* x   = (const float*)d_in[0];
    const int*   adj = (const int*)d_in[1];
    const float* W   = (const float*)d_in[2];
    const float* a   = (const float*)d_in[3];
    float* out = (float*)d_out;

    prep_kernel<<<NT / 16, 128>>>(x, W, a);
    attn_kernel<<<dim3(64, SPLITS), 256>>>(adj);
    finalize_kernel<<<(NT * OUT_FEAT) / 256, 256>>>(out);
}

// round 9
// speedup vs baseline: 1.4533x; 1.1202x over previous
#include <cuda_runtime.h>
#include <cuda_fp16.h>
#include <cstdint>
#include <cstddef>

// ============================================================
// GAT attention head, N=8192, IN_F=128, OUT_F=64
//  h = X@W ; e = LeakyReLU(fs_i + fd_j) masked by adj ; softmax ; P@h ; elu
//
// exp(LR(fs+fd)) = max(E_i*E_j, G_i*G_j), E=exp(f), G=exp(0.2f)
// -> no transcendental in the N^2 loop. Fixed-max softmax -> single pass;
// fp16 P/h via mma.sync.m16n8k16, fp32 accumulators + denominators.
//
// sigma j-permutation: k=2q->j=4q, k=2q+1->j=4q+1, k=2q+8->j=4q+2, k=2q+9->j=4q+3
//  A-frag (P): lane's 4 j contiguous; B-frag words adjacent (one LDS.64).
// adj + H + EG all staged gmem->smem via cp.async, double-buffered:
// loads stay in flight during compute -> DRAM duty cycle ~1.
// ============================================================

#define NT 8192
#define IN_FEAT 128
#define OUT_FEAT 64
#define SPLITS 8
#define JSPAN (NT / SPLITS)      // 1024
#define JTILE 64
#define NTILES (JSPAN / JTILE)   // 16
#define ADJROW 320               // 64*4 + 64 pad: LDS.128 conflict-free
#define HROW 160                 // 64*2 + 32 pad: LDS.64 conflict-free

#define ADJ_BYTES (128 * ADJROW)         // 40960
#define H_BYTES   (OUT_FEAT * HROW)      // 10240
#define EG_BYTES  (JTILE * 8)            // 512
#define OFF_ADJ0  0
#define OFF_ADJ1  (ADJ_BYTES)
#define OFF_H0    (2 * ADJ_BYTES)
#define OFF_H1    (2 * ADJ_BYTES + H_BYTES)
#define OFF_EG0   (2 * ADJ_BYTES + 2 * H_BYTES)
#define OFF_EG1   (OFF_EG0 + EG_BYTES)
#define ATTN_SMEM (OFF_EG1 + EG_BYTES)   // 103424

#define PREP_WS   0
#define PREP_XS   (IN_FEAT * OUT_FEAT * 4)            // 32768
#define PREP_HS   (PREP_XS + 32 * IN_FEAT * 4)        // 49152
#define HS_STRIDE 34
#define PREP_SMEM (PREP_HS + OUT_FEAT * HS_STRIDE * 2) // 53504

// ---------------- scratch (static device arrays; no allocation) ----------
__device__ __half g_ht[OUT_FEAT * NT];          // h transposed fp16: [f][j]
__device__ float2 g_EGs[NT];
__device__ float2 g_EGd[NT];
__device__ float  g_num[SPLITS * NT * OUT_FEAT];
__device__ float  g_den[SPLITS * NT];

// ---------------- helpers ------------------------------------------------
__device__ __forceinline__ uint32_t smem_u32(const void* p) {
    uint32_t a;
    asm("{ .reg .u64 t; cvta.to.shared.u64 t, %1; cvt.u32.u64 %0, t; }"
        : "=r"(a) : "l"(p));
    return a;
}
__device__ __forceinline__ void cp16(uint32_t dst, const void* src) {
    asm volatile("cp.async.cg.shared.global [%0], [%1], 16;" :: "r"(dst), "l"(src));
}
__device__ __forceinline__ void cp8(uint32_t dst, const void* src) {
    asm volatile("cp.async.ca.shared.global [%0], [%1], 8;" :: "r"(dst), "l"(src));
}
#define CP_COMMIT() asm volatile("cp.async.commit_group;" ::: "memory")
#define CP_WAIT0()  asm volatile("cp.async.wait_group 0;" ::: "memory")
#define CP_WAIT1()  asm volatile("cp.async.wait_group 1;" ::: "memory")

__device__ __forceinline__ void mma16816(float* d, uint32_t a0, uint32_t a1,
                                         uint32_t a2, uint32_t a3,
                                         uint32_t b0, uint32_t b1) {
    asm volatile(
        "mma.sync.aligned.m16n8k16.row.col.f32.f16.f16.f32 "
        "{%0,%1,%2,%3}, {%4,%5,%6,%7}, {%8,%9}, {%0,%1,%2,%3};"
        : "+f"(d[0]), "+f"(d[1]), "+f"(d[2]), "+f"(d[3])
        : "r"(a0), "r"(a1), "r"(a2), "r"(a3), "r"(b0), "r"(b1));
}
__device__ __forceinline__ uint32_t packh2(float x, float y) {
    __half2 h = __floats2half2_rn(x, y);
    return *reinterpret_cast<uint32_t*>(&h);
}

// =========================================================================
// Kernel 1: h = X@W ; EG tables ; h^T fp16 (coalesced via smem transpose).
// 256 blocks x 256 threads; 32 rows/block; warp owns 4 rows.
// =========================================================================
__global__ void __launch_bounds__(256) prep_kernel(const float* __restrict__ x,
                                                   const float* __restrict__ W,
                                                   const float* __restrict__ a) {
    extern __shared__ __align__(16) char sm[];
    float*  Ws = (float*)(sm + PREP_WS);
    float*  xs = (float*)(sm + PREP_XS);
    __half* hs = (__half*)(sm + PREP_HS);   // [64 f][34] (i_local padded)

    int tid = threadIdx.x;
    int i0 = blockIdx.x * 32;

    {
        const float4* W4 = (const float4*)W;
        float4* Ws4 = (float4*)Ws;
#pragma unroll
        for (int u = 0; u < 8; u++) Ws4[tid + u * 256] = W4[tid + u * 256];
        const float4* x4 = (const float4*)(x + (size_t)i0 * IN_FEAT);
        float4* xs4 = (float4*)xs;
#pragma unroll
        for (int u = 0; u < 4; u++) xs4[tid + u * 256] = x4[tid + u * 256];
    }
    __syncthreads();

    int w = tid >> 5, l = tid & 31;       // warp w: rows w*4 .. w*4+3
    float acc[4][2];
#pragma unroll
    for (int rr = 0; rr < 4; rr++) { acc[rr][0] = 0.f; acc[rr][1] = 0.f; }

#pragma unroll 4
    for (int k4 = 0; k4 < IN_FEAT; k4 += 4) {
        float2 wv[4];
#pragma unroll
        for (int kk = 0; kk < 4; kk++)
            wv[kk] = *(const float2*)&Ws[(k4 + kk) * OUT_FEAT + 2 * l];
#pragma unroll
        for (int rr = 0; rr < 4; rr++) {
            float4 xv = *(const float4*)&xs[(w * 4 + rr) * IN_FEAT + k4];
            acc[rr][0] = fmaf(xv.x, wv[0].x, acc[rr][0]);
            acc[rr][1] = fmaf(xv.x, wv[0].y, acc[rr][1]);
            acc[rr][0] = fmaf(xv.y, wv[1].x, acc[rr][0]);
            acc[rr][1] = fmaf(xv.y, wv[1].y, acc[rr][1]);
            acc[rr][0] = fmaf(xv.z, wv[2].x, acc[rr][0]);
            acc[rr][1] = fmaf(xv.z, wv[2].y, acc[rr][1]);
            acc[rr][0] = fmaf(xv.w, wv[3].x, acc[rr][0]);
            acc[rr][1] = fmaf(xv.w, wv[3].y, acc[rr][1]);
        }
    }

    // h -> smem transpose tile
#pragma unroll
    for (int rr = 0; rr < 4; rr++) {
        int il = w * 4 + rr;
        hs[(2 * l) * HS_STRIDE + il]     = __float2half(acc[rr][0]);
        hs[(2 * l + 1) * HS_STRIDE + il] = __float2half(acc[rr][1]);
    }

    float a0 = a[2 * l], a1 = a[2 * l + 1];
    float a2 = a[OUT_FEAT + 2 * l], a3 = a[OUT_FEAT + 2 * l + 1];
#pragma unroll
    for (int rr = 0; rr < 4; rr++) {
        float s = acc[rr][0] * a0 + acc[rr][1] * a1;
        float d = acc[rr][0] * a2 + acc[rr][1] * a3;
#pragma unroll
        for (int off = 16; off; off >>= 1) {
            s += __shfl_xor_sync(0xFFFFFFFFu, s, off);
            d += __shfl_xor_sync(0xFFFFFFFFu, d, off);
        }
        if (l == 0) {
            int i = i0 + w * 4 + rr;
            g_EGs[i] = make_float2(expf(s), expf(0.2f * s));
            g_EGd[i] = make_float2(expf(d), expf(0.2f * d));
        }
    }
    __syncthreads();

    // coalesced writeout: 64 f x 16 half2 chunks
#pragma unroll
    for (int u = 0; u < 4; u++) {
        int id = tid + u * 256;
        int f = id >> 4, c = id & 15;
        uint32_t v = *(const uint32_t*)&hs[f * HS_STRIDE + 2 * c];
        *(uint32_t*)&g_ht[(size_t)f * NT + i0 + 2 * c] = v;
    }
}

// =========================================================================
// Kernel 2: fused masked-softmax attention; adj/H/EG via cp.async pipeline.
// grid (64 row-blocks, SPLITS) = 512 CTAs, 256 thr, 2 CTAs/SM (smem-limited).
// =========================================================================
__global__ void __launch_bounds__(256) attn_kernel(const int* __restrict__ adj) {
    extern __shared__ __align__(16) char sm[];
    uint32_t sb = smem_u32(sm);

    int tid = threadIdx.x, w = tid >> 5, lane = tid & 31;
    int r = lane >> 2, q = lane & 3;
    int i0 = blockIdx.x * 128;
    int split = blockIdx.y;
    int jbase = split * JSPAN;

    int R0 = i0 + w * 16 + r;
    float2 egs0 = g_EGs[R0];
    float2 egs1 = g_EGs[R0 + 8];

    float acc[8][4];
#pragma unroll
    for (int nt = 0; nt < 8; nt++)
#pragma unroll
        for (int v = 0; v < 4; v++) acc[nt][v] = 0.f;
    float ds0 = 0.f, ds1 = 0.f;

    // stage one tile: adj (128x64 int) + H (64x64 fp16) + EG (64 float2)
    auto issue_tile = [&](int buf, int j0) {
        uint32_t ab = sb + (buf ? OFF_ADJ1 : OFF_ADJ0);
        uint32_t hb = sb + (buf ? OFF_H1 : OFF_H0);
        uint32_t eb = sb + (buf ? OFF_EG1 : OFF_EG0);
#pragma unroll
        for (int u = 0; u < 8; u++) {           // adj: 2048 chunks / 256 thr
            int id = tid + u * 256;
            int row = id >> 4, c = id & 15;
            cp16(ab + row * ADJROW + c * 16,
                 &adj[(size_t)(i0 + row) * NT + j0 + c * 4]);
        }
#pragma unroll
        for (int u = 0; u < 2; u++) {           // H: 512 chunks
            int id = tid + u * 256;
            int f = id >> 3, c = id & 7;
            cp16(hb + f * HROW + c * 16,
                 &g_ht[(size_t)f * NT + j0 + c * 8]);
        }
        if (tid < JTILE) cp8(eb + tid * 8, &g_EGd[j0 + tid]);
        CP_COMMIT();
    };

    issue_tile(0, jbase);

    for (int t = 0; t < NTILES; t++) {
        int b = t & 1;
        __syncthreads();                        // buffer b^1 free for prefetch
        if (t + 1 < NTILES) { issue_tile(b ^ 1, jbase + (t + 1) * JTILE); CP_WAIT1(); }
        else                { CP_WAIT0(); }
        __syncthreads();                        // tile t visible to all warps

        const char* ab = sm + (b ? OFF_ADJ1 : OFF_ADJ0);
        const char* hb = sm + (b ? OFF_H1 : OFF_H0);
        const float2* eb = (const float2*)(sm + (b ? OFF_EG1 : OFF_EG0));

#pragma unroll
        for (int kk = 0; kk < 4; kk++) {
            int jloc = kk * 16 + 4 * q;
            int4 avA = *(const int4*)(ab + (w * 16 + r) * ADJROW + kk * 64 + q * 16);
            int4 avB = *(const int4*)(ab + (w * 16 + r + 8) * ADJROW + kk * 64 + q * 16);
            float4 egA = *(const float4*)&eb[jloc];
            float4 egB = *(const float4*)&eb[jloc + 2];

            float p00 = avA.x ? fmaxf(egs0.x * egA.x, egs0.y * egA.y) : 0.f;
            float p01 = avA.y ? fmaxf(egs0.x * egA.z, egs0.y * egA.w) : 0.f;
            float p02 = avA.z ? fmaxf(egs0.x * egB.x, egs0.y * egB.y) : 0.f;
            float p03 = avA.w ? fmaxf(egs0.x * egB.z, egs0.y * egB.w) : 0.f;
            float p10 = avB.x ? fmaxf(egs1.x * egA.x, egs1.y * egA.y) : 0.f;
            float p11 = avB.y ? fmaxf(egs1.x * egA.z, egs1.y * egA.w) : 0.f;
            float p12 = avB.z ? fmaxf(egs1.x * egB.x, egs1.y * egB.y) : 0.f;
            float p13 = avB.w ? fmaxf(egs1.x * egB.z, egs1.y * egB.w) : 0.f;

            ds0 += (p00 + p01) + (p02 + p03);
            ds1 += (p10 + p11) + (p12 + p13);

            uint32_t A0 = packh2(p00, p01);
            uint32_t A1 = packh2(p10, p11);
            uint32_t A2 = packh2(p02, p03);
            uint32_t A3 = packh2(p12, p13);

            int ko = kk * 32 + q * 8;
#pragma unroll
            for (int nt = 0; nt < 8; nt++) {
                uint2 bb = *(const uint2*)(hb + (nt * 8 + r) * HROW + ko);
                mma16816(acc[nt], A0, A1, A2, A3, bb.x, bb.y);
            }
        }
    }

    // denominator: reduce over the 4 lanes (q) sharing a row
    ds0 += __shfl_xor_sync(0xFFFFFFFFu, ds0, 1);
    ds0 += __shfl_xor_sync(0xFFFFFFFFu, ds0, 2);
    ds1 += __shfl_xor_sync(0xFFFFFFFFu, ds1, 1);
    ds1 += __shfl_xor_sync(0xFFFFFFFFu, ds1, 2);
    if (q == 0) {
        g_den[(size_t)split * NT + R0]     = ds0;
        g_den[(size_t)split * NT + R0 + 8] = ds1;
    }

    float* gn = &g_num[(size_t)split * NT * OUT_FEAT];
#pragma unroll
    for (int nt = 0; nt < 8; nt++) {
        int col = nt * 8 + q * 2;
        *(float2*)&gn[(size_t)R0 * OUT_FEAT + col]       = make_float2(acc[nt][0], acc[nt][1]);
        *(float2*)&gn[(size_t)(R0 + 8) * OUT_FEAT + col] = make_float2(acc[nt][2], acc[nt][3]);
    }
}

// =========================================================================
// Kernel 3: combine split partials, divide, elu
// =========================================================================
__global__ void __launch_bounds__(256) finalize_kernel(float* __restrict__ out) {
    size_t idx = (size_t)blockIdx.x * 256 + threadIdx.x;
    size_t i = idx >> 6;
    float num = 0.f, den = 0.f;
#pragma unroll
    for (int s = 0; s < SPLITS; s++) {
        num += g_num[(size_t)s * NT * OUT_FEAT + idx];
        den += g_den[(size_t)s * NT + i];
    }
    den = fmaxf(den, 1e-30f);
    float v = num / den;
    out[idx] = v > 0.f ? v : expm1f(v);
}

// =========================================================================
extern "C" void kernel_launch(void* const* d_in, const int* in_sizes, int n_in,
                              void* d_out, int out_size) {
    const float* x   = (const float*)d_in[0];
    const int*   adj = (const int*)d_in[1];
    const float* W   = (const float*)d_in[2];
    const float* a   = (const float*)d_in[3];
    float* out = (float*)d_out;

    cudaFuncSetAttribute(prep_kernel, cudaFuncAttributeMaxDynamicSharedMemorySize,
                         PREP_SMEM);
    cudaFuncSetAttribute(attn_kernel, cudaFuncAttributeMaxDynamicSharedMemorySize,
                         ATTN_SMEM);

    prep_kernel<<<NT / 32, 256, PREP_SMEM>>>(x, W, a);
    attn_kernel<<<dim3(64, SPLITS), 256, ATTN_SMEM>>>(adj);
    finalize_kernel<<<(NT * OUT_FEAT) / 256, 256>>>(out);
}